// round 9
// baseline (speedup 1.0000x reference)
#include <cuda_runtime.h>
#include <stdint.h>
#include <math_constants.h>

#define K_CODES 8192
#define DIM     256
#define NTOK    32768
#define HW      1024

// output layout (floats): loss | quantized | indices | new_count | new_weight | new_codebook
#define OUT_LOSS 0
#define OUT_Q    1
#define OUT_IDX  (OUT_Q  + 32*DIM*HW)
#define OUT_CNT  (OUT_IDX + NTOK)
#define OUT_W    (OUT_CNT + K_CODES)
#define OUT_CB   (OUT_W   + K_CODES*DIM)

// ---------------- device scratch ----------------
__device__ __align__(128) float g_xhi[NTOK * DIM];      // x layout: [b][d][hw]
__device__ __align__(128) float g_xlo[NTOK * DIM];
__device__ __align__(128) float g_cbhiT[DIM * K_CODES]; // transposed: [d][code]
__device__ __align__(128) float g_cbloT[DIM * K_CODES];
__device__ float              g_cbnorm[K_CODES];
__device__ float              g_znorm[NTOK];
__device__ double             g_zpart[4][NTOK];
__device__ unsigned long long g_best[NTOK];
__device__ float              g_counts[K_CODES];
__device__ float              g_dw[K_CODES * DIM];
__device__ double             g_loss;
__device__ int                g_idx[NTOK];

__device__ __forceinline__ uint32_t smem_u32(const void* p) {
    uint32_t a;
    asm("{ .reg .u64 t; cvta.to.shared.u64 t, %1; cvt.u32.u64 %0, t; }" : "=r"(a) : "l"(p));
    return a;
}
__device__ __forceinline__ float to_tf32(float v) {
    uint32_t u;
    asm("cvt.rna.satfinite.tf32.f32 %0, %1;" : "=r"(u) : "f"(v));
    return __uint_as_float(u);
}
#define CP16(dst, src) \
    asm volatile("cp.async.ca.shared.global [%0], [%1], 16;" :: "r"(dst), "l"(src))
#define CP_COMMIT() asm volatile("cp.async.commit_group;" ::: "memory")
#define CP_WAIT1()  asm volatile("cp.async.wait_group 1;" ::: "memory")
#define CP_WAIT0()  asm volatile("cp.async.wait_group 0;" ::: "memory")

#define MMA_TF32(c, a, b) \
    asm volatile("mma.sync.aligned.m16n8k8.row.col.f32.tf32.tf32.f32 " \
        "{%0,%1,%2,%3}, {%4,%5,%6,%7}, {%8,%9}, {%0,%1,%2,%3};" \
        : "+f"((c)[0]), "+f"((c)[1]), "+f"((c)[2]), "+f"((c)[3]) \
        : "r"((a)[0]), "r"((a)[1]), "r"((a)[2]), "r"((a)[3]), "r"((b)[0]), "r"((b)[1]))

// ---------------- init ----------------
__global__ void init_kernel() {
    int i = blockIdx.x * blockDim.x + threadIdx.x;
    if (i < K_CODES * DIM) g_dw[i] = 0.0f;
    if (i < NTOK)          g_best[i] = 0xFFFFFFFFFFFFFFFFull;
    if (i < K_CODES)       g_counts[i] = 0.0f;
    if (i == 0)            g_loss = 0.0;
}

// ---------------- decompose x -> tf32 hi/lo (same layout) ----------------
__global__ void decomp_x(const float* __restrict__ x) {
    int i = blockIdx.x * blockDim.x + threadIdx.x;
    float v  = x[i];
    float hi = to_tf32(v);
    g_xhi[i] = hi;
    g_xlo[i] = to_tf32(v - hi);
}

// ---------------- decompose + transpose codebook -> [d][code] hi/lo ----------------
__global__ void decomp_cbT(const float* __restrict__ cb) {
    __shared__ float tile[32][33];
    int tx = threadIdx.x, ty = threadIdx.y;
    int c0 = blockIdx.x * 32, d0 = blockIdx.y * 32;
    tile[ty][tx] = cb[(size_t)(c0 + ty) * DIM + d0 + tx];
    __syncthreads();
    float v  = tile[tx][ty];                  // code = c0+tx, d = d0+ty
    float hi = to_tf32(v);
    size_t o = (size_t)(d0 + ty) * K_CODES + c0 + tx;
    g_cbhiT[o] = hi;
    g_cbloT[o] = to_tf32(v - hi);
}

// ---------------- token norm partials: chunk c sums d in [c*64, c*64+64) ------
__global__ void znorm_part(const float* __restrict__ x) {
    int token = blockIdx.x * blockDim.x + threadIdx.x;
    int c = blockIdx.y;
    int b = token >> 10, hw = token & 1023;
    const float* p = x + (size_t)b * DIM * HW + (size_t)(c * 64) * HW + hw;
    double s0 = 0.0, s1 = 0.0, s2 = 0.0, s3 = 0.0;
    #pragma unroll 4
    for (int d = 0; d < 64; d += 4) {
        double v0 = (double)p[(size_t)(d + 0) * HW];
        double v1 = (double)p[(size_t)(d + 1) * HW];
        double v2 = (double)p[(size_t)(d + 2) * HW];
        double v3 = (double)p[(size_t)(d + 3) * HW];
        s0 = fma(v0, v0, s0);
        s1 = fma(v1, v1, s1);
        s2 = fma(v2, v2, s2);
        s3 = fma(v3, v3, s3);
    }
    g_zpart[c][token] = ((s0 + s1) + (s2 + s3));
}

__global__ void znorm_comb() {
    int token = blockIdx.x * blockDim.x + threadIdx.x;
    g_znorm[token] = (float)((g_zpart[0][token] + g_zpart[1][token])
                           + (g_zpart[2][token] + g_zpart[3][token]));
}

// ---------------- codebook norms (fp64 -> fp32) ----------------
__global__ void cbnorm_kernel(const float* __restrict__ cb) {
    int gt = blockIdx.x * blockDim.x + threadIdx.x;
    int code = gt >> 5, lane = gt & 31;
    if (code >= K_CODES) return;
    const float* r = cb + (size_t)code * DIM;
    double s = 0.0;
    #pragma unroll
    for (int i = lane; i < DIM; i += 32) {
        double v = (double)__ldg(r + i);
        s = fma(v, v, s);
    }
    #pragma unroll
    for (int o = 16; o; o >>= 1) s += __shfl_down_sync(0xFFFFFFFFu, s, o);
    if (lane == 0) g_cbnorm[code] = (float)s;
}

// ---------------- 3xTF32 mma.sync distance GEMM + argmin ----------------
// grid (64, 256): 128 codes x 128 tokens per CTA; BK=32, 3-stage cp.async,
// ONE __syncthreads per k-step. smem per stage: Ahi|Alo|Bhi|Blo, 32x136f each.
#define ROWP    136
#define ARR_F   (32 * ROWP)          // 4352 floats per array
#define STAGE_F (4 * ARR_F)          // 17408 floats per stage
#define NSTAGE  3
#define SMEM_B  (NSTAGE * STAGE_F * 4)   // 208896 bytes

__global__ void __launch_bounds__(256, 1)
gemm_argmin_tc(void) {
    extern __shared__ float smf[];
    const uint32_t smb = smem_u32(smf);

    const int tid  = threadIdx.x;
    const int lane = tid & 31;
    const int wid  = tid >> 5;
    const int g    = lane >> 2;        // 0..7
    const int q    = lane & 3;         // 0..3

    const int tb  = blockIdx.y;                   // token tile
    const int ct  = blockIdx.x;                   // code tile
    const int b   = (tb * 128) >> 10;
    const int hw0 = (tb * 128) & 1023;
    const int nt0 = ct * 128;

    const int mbase = (wid & 3) * 32;   // warp token offset
    const int nbase = (wid >> 2) * 64;  // warp code offset

    float acc[2][8][4];
    #pragma unroll
    for (int mf = 0; mf < 2; mf++)
        #pragma unroll
        for (int nf = 0; nf < 8; nf++)
            #pragma unroll
            for (int c = 0; c < 4; c++) acc[mf][nf][c] = 0.0f;

    // stage issue: each array tile = 32 rows x 128 floats = 1024 float4;
    // 256 threads x 4 float4 per array. smem row pitch ROWP=136 floats.
    auto issue = [&](int s, int k0) {
        const float* srcA[2] = {
            g_xhi + ((size_t)(b * DIM + k0) << 10) + hw0,
            g_xlo + ((size_t)(b * DIM + k0) << 10) + hw0 };
        const float* srcB[2] = {
            g_cbhiT + ((size_t)k0 << 13) + nt0,
            g_cbloT + ((size_t)k0 << 13) + nt0 };
        #pragma unroll
        for (int arr = 0; arr < 4; arr++) {
            const float* bp = (arr < 2) ? srcA[arr] : srcB[arr - 2];
            const size_t rstride = (arr < 2) ? 1024 : 8192;  // gmem row stride (floats)
            #pragma unroll
            for (int i = 0; i < 4; i++) {
                int idx = i * 256 + tid;         // 0..1023
                int row = idx >> 5;              // 0..31
                int seg = (idx & 31) * 4;        // 0..124
                uint32_t dst = smb + 4u * (s * STAGE_F + arr * ARR_F + row * ROWP + seg);
                CP16(dst, bp + (size_t)row * rstride + seg);
            }
        }
        CP_COMMIT();
    };

    issue(0, 0);
    issue(1, 32);

    #pragma unroll 1
    for (int ks = 0; ks < 8; ks++) {
        if (ks < 7) CP_WAIT1(); else CP_WAIT0();
        __syncthreads();                       // single barrier per k-step
        if (ks < 6) issue((ks + 2) % NSTAGE, (ks + 2) * 32);

        const uint32_t* Ah = (const uint32_t*)(smf + (ks % NSTAGE) * STAGE_F);
        const uint32_t* Al = Ah + ARR_F;
        const uint32_t* Bh = Al + ARR_F;
        const uint32_t* Bl = Bh + ARR_F;

        #pragma unroll
        for (int kk = 0; kk < 4; kk++) {
            const int r0 = kk * 8 + q;
            const int r1 = r0 + 4;
            uint32_t afh[2][4], afl[2][4], bfh[8][2], bfl[8][2];
            #pragma unroll
            for (int mf = 0; mf < 2; mf++) {
                int m = mbase + mf * 16 + g;
                afh[mf][0] = Ah[r0 * ROWP + m];
                afh[mf][1] = Ah[r0 * ROWP + m + 8];
                afh[mf][2] = Ah[r1 * ROWP + m];
                afh[mf][3] = Ah[r1 * ROWP + m + 8];
                afl[mf][0] = Al[r0 * ROWP + m];
                afl[mf][1] = Al[r0 * ROWP + m + 8];
                afl[mf][2] = Al[r1 * ROWP + m];
                afl[mf][3] = Al[r1 * ROWP + m + 8];
            }
            #pragma unroll
            for (int nf = 0; nf < 8; nf++) {
                int n = nbase + nf * 8 + g;
                bfh[nf][0] = Bh[r0 * ROWP + n];
                bfh[nf][1] = Bh[r1 * ROWP + n];
                bfl[nf][0] = Bl[r0 * ROWP + n];
                bfl[nf][1] = Bl[r1 * ROWP + n];
            }
            // per-acc term order (hi*hi, hi*lo, lo*hi) identical to R6/R8.
            #pragma unroll
            for (int mf = 0; mf < 2; mf++)
                #pragma unroll
                for (int nf = 0; nf < 8; nf++)
                    MMA_TF32(acc[mf][nf], afh[mf], bfh[nf]);  // hi*hi
            #pragma unroll
            for (int mf = 0; mf < 2; mf++)
                #pragma unroll
                for (int nf = 0; nf < 8; nf++)
                    MMA_TF32(acc[mf][nf], afh[mf], bfl[nf]);  // hi*lo
            #pragma unroll
            for (int mf = 0; mf < 2; mf++)
                #pragma unroll
                for (int nf = 0; nf < 8; nf++)
                    MMA_TF32(acc[mf][nf], afl[mf], bfh[nf]);  // lo*hi
        }
    }

    // epilogue: d = fl( fl(zn+cn) - 2*dot ), lexicographic (d, idx) min.
    // C frag: c0/c1 at row g (cols 2q, 2q+1), c2/c3 at row g+8.
    #pragma unroll
    for (int mf = 0; mf < 2; mf++) {
        #pragma unroll
        for (int h = 0; h < 2; h++) {
            int m = mbase + mf * 16 + g + h * 8;
            int token = tb * 128 + m;
            float zn = g_znorm[token];
            unsigned long long bestpk = 0xFFFFFFFFFFFFFFFFull;
            #pragma unroll
            for (int nf = 0; nf < 8; nf++) {
                #pragma unroll
                for (int p = 0; p < 2; p++) {
                    int n = nbase + nf * 8 + q * 2 + p;
                    float dot = acc[mf][nf][h * 2 + p];
                    float cn  = __ldg(&g_cbnorm[nt0 + n]);
                    float t1  = __fadd_rn(zn, cn);
                    float d   = __fsub_rn(t1, __fmul_rn(2.0f, dot));
                    unsigned int e = __float_as_uint(d);
                    e = (e & 0x80000000u) ? ~e : (e | 0x80000000u);
                    unsigned long long pk =
                        ((unsigned long long)e << 32) | (unsigned int)(nt0 + n);
                    if (pk < bestpk) bestpk = pk;
                }
            }
            atomicMin(&g_best[token], bestpk);
        }
    }
}

// ---------------- extract indices, bump counts ----------------
__global__ void post_idx(float* __restrict__ out) {
    int n = blockIdx.x * blockDim.x + threadIdx.x;
    if (n >= NTOK) return;
    unsigned long long pk = g_best[n];
    int id = (int)(pk & 0xFFFFFFFFull);
    g_idx[n] = id;
    out[OUT_IDX + n] = (float)id;
    atomicAdd(&g_counts[id], 1.0f);
}

// ---------------- quantized output + commitment loss (coalesced) ----------------
// grid (DIM, 32): block = (c, b); 256 threads x 4 iters over hw.
__global__ void quant_loss(const float* __restrict__ x,
                           const float* __restrict__ cb,
                           float* __restrict__ out) {
    int c = blockIdx.x, b = blockIdx.y;
    int tid = threadIdx.x, lane = tid & 31;
    float ls = 0.0f;
    #pragma unroll
    for (int it = 0; it < 4; it++) {
        int hw = it * 256 + tid;
        int n  = (b << 10) + hw;
        int id = g_idx[n];
        float qv = __ldg(cb + (size_t)id * DIM + c);
        size_t off = (size_t)b * DIM * HW + (size_t)c * HW + hw;
        float xv = x[off];
        out[OUT_Q + off] = __fadd_rn(xv, __fsub_rn(qv, xv));
        float d = __fsub_rn(qv, xv);
        ls = fmaf(d, d, ls);
    }
    double ds = (double)ls;
    #pragma unroll
    for (int o = 16; o; o >>= 1) ds += __shfl_down_sync(0xFFFFFFFFu, ds, o);
    if (lane == 0) atomicAdd(&g_loss, ds);
}

// ---------------- dw = segment_sum(flat, idx) ----------------
__global__ void dw_kernel(const float* __restrict__ x) {
    int n = blockIdx.x * blockDim.x + threadIdx.x;
    int d = blockIdx.y;
    int b = n >> 10, hw = n & 1023;
    float v = x[(size_t)b * DIM * HW + (size_t)d * HW + hw];
    atomicAdd(&g_dw[(size_t)g_idx[n] * DIM + d], v);
}

// ---------------- EMA finalize ----------------
__global__ void final_kernel(const float* __restrict__ ema_count,
                             const float* __restrict__ ema_weight,
                             float* __restrict__ out) {
    int k = blockIdx.x;
    int c = threadIdx.x;
    float nc = ema_count[k] * 0.95f + 0.05f * g_counts[k];
    const float denom = (float)(32768.0 + 8192.0 * 1e-5);
    nc = (nc + 1e-5f) / denom * 32768.0f;
    float w = ema_weight[(size_t)k * DIM + c] * 0.95f + 0.05f * g_dw[(size_t)k * DIM + c];
    out[OUT_W  + (size_t)k * DIM + c] = w;
    out[OUT_CB + (size_t)k * DIM + c] = w / nc;
    if (c == 0) out[OUT_CNT + k] = nc;
    if (k == 0 && c == 0) {
        double mean = g_loss / (double)((size_t)NTOK * DIM);
        out[OUT_LOSS] = 0.25f * (float)mean;
    }
}

extern "C" void kernel_launch(void* const* d_in, const int* in_sizes, int n_in,
                              void* d_out, int out_size) {
    const float* x          = (const float*)d_in[0];
    const float* cb         = (const float*)d_in[1];
    const float* ema_count  = (const float*)d_in[2];
    const float* ema_weight = (const float*)d_in[3];
    float* out = (float*)d_out;

    static int smem_set = 0;
    if (!smem_set) {
        cudaFuncSetAttribute(gemm_argmin_tc,
                             cudaFuncAttributeMaxDynamicSharedMemorySize, SMEM_B);
        smem_set = 1;
    }

    init_kernel<<<(K_CODES * DIM + 255) / 256, 256>>>();
    decomp_x<<<NTOK * DIM / 256, 256>>>(x);
    decomp_cbT<<<dim3(K_CODES / 32, DIM / 32), dim3(32, 32)>>>(cb);
    znorm_part<<<dim3(NTOK / 256, 4), 256>>>(x);
    znorm_comb<<<NTOK / 256, 256>>>();
    cbnorm_kernel<<<(K_CODES * 32 + 255) / 256, 256>>>(cb);
    gemm_argmin_tc<<<dim3(K_CODES / 128, NTOK / 128), 256, SMEM_B>>>();
    post_idx<<<NTOK / 256, 256>>>(out);
    quant_loss<<<dim3(DIM, 32), 256>>>(x, cb, out);
    dw_kernel<<<dim3(NTOK / 256, DIM), 256>>>(x);
    final_kernel<<<K_CODES, DIM>>>(ema_count, ema_weight, out);
}

// round 11
// speedup vs baseline: 1.1185x; 1.1185x over previous
#include <cuda_runtime.h>
#include <stdint.h>
#include <math_constants.h>

#define K_CODES 8192
#define DIM     256
#define NTOK    32768
#define HW      1024

// output layout (floats): loss | quantized | indices | new_count | new_weight | new_codebook
#define OUT_LOSS 0
#define OUT_Q    1
#define OUT_IDX  (OUT_Q  + 32*DIM*HW)
#define OUT_CNT  (OUT_IDX + NTOK)
#define OUT_W    (OUT_CNT + K_CODES)
#define OUT_CB   (OUT_W   + K_CODES*DIM)

// ---------------- device scratch ----------------
__device__ __align__(128) float g_xhi[NTOK * DIM];      // x layout: [b][d][hw]
__device__ __align__(128) float g_xlo[NTOK * DIM];
__device__ __align__(128) float g_cbhiT[DIM * K_CODES]; // transposed: [d][code]
__device__ __align__(128) float g_cbloT[DIM * K_CODES];
__device__ float              g_cbnorm[K_CODES];
__device__ float              g_znorm[NTOK];
__device__ unsigned long long g_best[NTOK];
__device__ float              g_counts[K_CODES];
__device__ float              g_dw[K_CODES * DIM];
__device__ double             g_loss;
__device__ int                g_idx[NTOK];

__device__ __forceinline__ uint32_t smem_u32(const void* p) {
    uint32_t a;
    asm("{ .reg .u64 t; cvta.to.shared.u64 t, %1; cvt.u32.u64 %0, t; }" : "=r"(a) : "l"(p));
    return a;
}
__device__ __forceinline__ float to_tf32(float v) {
    uint32_t u;
    asm("cvt.rna.satfinite.tf32.f32 %0, %1;" : "=r"(u) : "f"(v));
    return __uint_as_float(u);
}
#define CP16(dst, src) \
    asm volatile("cp.async.ca.shared.global [%0], [%1], 16;" :: "r"(dst), "l"(src))
#define CP_COMMIT() asm volatile("cp.async.commit_group;" ::: "memory")
#define CP_WAIT0()  asm volatile("cp.async.wait_group 0;" ::: "memory")

#define MMA_TF32(c, a, b) \
    asm volatile("mma.sync.aligned.m16n8k8.row.col.f32.tf32.tf32.f32 " \
        "{%0,%1,%2,%3}, {%4,%5,%6,%7}, {%8,%9}, {%0,%1,%2,%3};" \
        : "+f"((c)[0]), "+f"((c)[1]), "+f"((c)[2]), "+f"((c)[3]) \
        : "r"((a)[0]), "r"((a)[1]), "r"((a)[2]), "r"((a)[3]), "r"((b)[0]), "r"((b)[1]))

// ---------------- init ----------------
__global__ void init_kernel() {
    int i = blockIdx.x * blockDim.x + threadIdx.x;
    if (i < K_CODES * DIM) g_dw[i] = 0.0f;
    if (i < NTOK)          g_best[i] = 0xFFFFFFFFFFFFFFFFull;
    if (i < K_CODES)       g_counts[i] = 0.0f;
    if (i == 0)            g_loss = 0.0;
}

// ---------------- decompose x -> tf32 hi/lo (float4 vectorized) ----------------
__global__ void decomp_x(const float4* __restrict__ x4) {
    int i = blockIdx.x * blockDim.x + threadIdx.x;
    float4 v = x4[i];
    float4 hi, lo;
    hi.x = to_tf32(v.x); lo.x = to_tf32(v.x - hi.x);
    hi.y = to_tf32(v.y); lo.y = to_tf32(v.y - hi.y);
    hi.z = to_tf32(v.z); lo.z = to_tf32(v.z - hi.z);
    hi.w = to_tf32(v.w); lo.w = to_tf32(v.w - hi.w);
    ((float4*)g_xhi)[i] = hi;
    ((float4*)g_xlo)[i] = lo;
}

// ---------------- decompose + transpose codebook -> [d][code] hi/lo ----------------
__global__ void decomp_cbT(const float* __restrict__ cb) {
    __shared__ float tile[32][33];
    int tx = threadIdx.x, ty = threadIdx.y;
    int c0 = blockIdx.x * 32, d0 = blockIdx.y * 32;
    tile[ty][tx] = cb[(size_t)(c0 + ty) * DIM + d0 + tx];
    __syncthreads();
    float v  = tile[tx][ty];                  // code = c0+tx, d = d0+ty
    float hi = to_tf32(v);
    size_t o = (size_t)(d0 + ty) * K_CODES + c0 + tx;
    g_cbhiT[o] = hi;
    g_cbloT[o] = to_tf32(v - hi);
}

// ---------------- token norms: float4 = 4 tokens/thread, d-sequential fp64 ------
__global__ void znorm_kernel(const float* __restrict__ x) {
    int t4 = blockIdx.x * blockDim.x + threadIdx.x;     // 0..8191
    int b   = t4 >> 8;
    int hw4 = t4 & 255;
    const float4* p = (const float4*)(x + (size_t)b * DIM * HW) + hw4;
    double s0 = 0.0, s1 = 0.0, s2 = 0.0, s3 = 0.0;
    #pragma unroll 8
    for (int d = 0; d < DIM; d++) {
        float4 v = p[(size_t)d * 256];
        double vx = (double)v.x, vy = (double)v.y, vz = (double)v.z, vw = (double)v.w;
        s0 = fma(vx, vx, s0);
        s1 = fma(vy, vy, s1);
        s2 = fma(vz, vz, s2);
        s3 = fma(vw, vw, s3);
    }
    int token = (b << 10) + hw4 * 4;
    g_znorm[token + 0] = (float)s0;
    g_znorm[token + 1] = (float)s1;
    g_znorm[token + 2] = (float)s2;
    g_znorm[token + 3] = (float)s3;
}

// ---------------- codebook norms (fp64 -> fp32) ----------------
__global__ void cbnorm_kernel(const float* __restrict__ cb) {
    int gt = blockIdx.x * blockDim.x + threadIdx.x;
    int code = gt >> 5, lane = gt & 31;
    if (code >= K_CODES) return;
    const float* r = cb + (size_t)code * DIM;
    double s = 0.0;
    #pragma unroll
    for (int i = lane; i < DIM; i += 32) {
        double v = (double)__ldg(r + i);
        s = fma(v, v, s);
    }
    #pragma unroll
    for (int o = 16; o; o >>= 1) s += __shfl_down_sync(0xFFFFFFFFu, s, o);
    if (lane == 0) g_cbnorm[code] = (float)s;
}

// ---------------- 3xTF32 mma.sync distance GEMM + argmin ----------------
// grid (64, 256): 128 codes x 128 tokens per CTA; BK=16, 2-stage cp.async,
// 2 CTAs/SM. Mainloop order: wait -> sync -> issue(next) -> compute(cur);
// the barrier separates all reads of a buffer from the next write into it.
#define ROWP    136
#define NKROW   16
#define ARR_F   (NKROW * ROWP)       // 2176 floats per array
#define STAGE_F (4 * ARR_F)          // 8704 floats per stage
#define SMEM_B  (2 * STAGE_F * 4)    // 69632 bytes
#define NKSTEP  16

__global__ void __launch_bounds__(256, 2)
gemm_argmin_tc(void) {
    extern __shared__ float smf[];
    const uint32_t smb = smem_u32(smf);

    const int tid  = threadIdx.x;
    const int lane = tid & 31;
    const int wid  = tid >> 5;
    const int g    = lane >> 2;        // 0..7
    const int q    = lane & 3;         // 0..3

    const int tb  = blockIdx.y;                   // token tile
    const int ct  = blockIdx.x;                   // code tile
    const int b   = (tb * 128) >> 10;
    const int hw0 = (tb * 128) & 1023;
    const int nt0 = ct * 128;

    const int mbase = (wid & 3) * 32;   // warp token offset
    const int nbase = (wid >> 2) * 64;  // warp code offset

    float acc[2][8][4];
    #pragma unroll
    for (int mf = 0; mf < 2; mf++)
        #pragma unroll
        for (int nf = 0; nf < 8; nf++)
            #pragma unroll
            for (int c = 0; c < 4; c++) acc[mf][nf][c] = 0.0f;

    // stage issue: each array tile = 16 rows x 128 floats = 512 float4;
    // 256 threads x 2 float4 per array (8 CP16/thread/stage total).
    auto issue = [&](int s, int k0) {
        const float* srcA[2] = {
            g_xhi + ((size_t)(b * DIM + k0) << 10) + hw0,
            g_xlo + ((size_t)(b * DIM + k0) << 10) + hw0 };
        const float* srcB[2] = {
            g_cbhiT + ((size_t)k0 << 13) + nt0,
            g_cbloT + ((size_t)k0 << 13) + nt0 };
        #pragma unroll
        for (int arr = 0; arr < 4; arr++) {
            const float* bp = (arr < 2) ? srcA[arr] : srcB[arr - 2];
            const size_t rstride = (arr < 2) ? 1024 : 8192;  // gmem row stride (floats)
            #pragma unroll
            for (int i = 0; i < 2; i++) {
                int idx = i * 256 + tid;         // 0..511
                int row = idx >> 5;              // 0..15
                int seg = (idx & 31) * 4;        // 0..124
                uint32_t dst = smb + 4u * (s * STAGE_F + arr * ARR_F + row * ROWP + seg);
                CP16(dst, bp + (size_t)row * rstride + seg);
            }
        }
        CP_COMMIT();
    };

    issue(0, 0);

    #pragma unroll 1
    for (int ks = 0; ks < NKSTEP; ks++) {
        CP_WAIT0();                          // stage ks resident
        __syncthreads();                     // also: all reads of buf (ks+1)&1 done
        if (ks < NKSTEP - 1) issue((ks + 1) & 1, (ks + 1) * NKROW);

        const uint32_t* Ah = (const uint32_t*)(smf + (ks & 1) * STAGE_F);
        const uint32_t* Al = Ah + ARR_F;
        const uint32_t* Bh = Al + ARR_F;
        const uint32_t* Bl = Bh + ARR_F;

        #pragma unroll
        for (int kk = 0; kk < 2; kk++) {
            const int r0 = kk * 8 + q;
            const int r1 = r0 + 4;
            // per-acc op order over 8-wide k-slices: hi*hi, hi*lo, lo*hi
            // (ascending k) — bit-identical to R6/R8 accumulation.
            uint32_t afh[2][4], bfh[8][2];
            #pragma unroll
            for (int mf = 0; mf < 2; mf++) {
                int m = mbase + mf * 16 + g;
                afh[mf][0] = Ah[r0 * ROWP + m];
                afh[mf][1] = Ah[r0 * ROWP + m + 8];
                afh[mf][2] = Ah[r1 * ROWP + m];
                afh[mf][3] = Ah[r1 * ROWP + m + 8];
            }
            #pragma unroll
            for (int nf = 0; nf < 8; nf++) {
                int n = nbase + nf * 8 + g;
                bfh[nf][0] = Bh[r0 * ROWP + n];
                bfh[nf][1] = Bh[r1 * ROWP + n];
            }
            #pragma unroll
            for (int mf = 0; mf < 2; mf++)
                #pragma unroll
                for (int nf = 0; nf < 8; nf++)
                    MMA_TF32(acc[mf][nf], afh[mf], bfh[nf]);  // hi*hi

            uint32_t bfl[8][2];
            #pragma unroll
            for (int nf = 0; nf < 8; nf++) {
                int n = nbase + nf * 8 + g;
                bfl[nf][0] = Bl[r0 * ROWP + n];
                bfl[nf][1] = Bl[r1 * ROWP + n];
            }
            #pragma unroll
            for (int mf = 0; mf < 2; mf++)
                #pragma unroll
                for (int nf = 0; nf < 8; nf++)
                    MMA_TF32(acc[mf][nf], afh[mf], bfl[nf]);  // hi*lo

            uint32_t afl[2][4];
            #pragma unroll
            for (int mf = 0; mf < 2; mf++) {
                int m = mbase + mf * 16 + g;
                afl[mf][0] = Al[r0 * ROWP + m];
                afl[mf][1] = Al[r0 * ROWP + m + 8];
                afl[mf][2] = Al[r1 * ROWP + m];
                afl[mf][3] = Al[r1 * ROWP + m + 8];
            }
            #pragma unroll
            for (int mf = 0; mf < 2; mf++)
                #pragma unroll
                for (int nf = 0; nf < 8; nf++)
                    MMA_TF32(acc[mf][nf], afl[mf], bfh[nf]);  // lo*hi
        }
    }

    // epilogue: d = fl( fl(zn+cn) - 2*dot ), lexicographic (d, idx) min.
    // C frag: c0/c1 at row g (cols 2q, 2q+1), c2/c3 at row g+8.
    #pragma unroll
    for (int mf = 0; mf < 2; mf++) {
        #pragma unroll
        for (int h = 0; h < 2; h++) {
            int m = mbase + mf * 16 + g + h * 8;
            int token = tb * 128 + m;
            float zn = g_znorm[token];
            unsigned long long bestpk = 0xFFFFFFFFFFFFFFFFull;
            #pragma unroll
            for (int nf = 0; nf < 8; nf++) {
                #pragma unroll
                for (int p = 0; p < 2; p++) {
                    int n = nbase + nf * 8 + q * 2 + p;
                    float dot = acc[mf][nf][h * 2 + p];
                    float cn  = __ldg(&g_cbnorm[nt0 + n]);
                    float t1  = __fadd_rn(zn, cn);
                    float d   = __fsub_rn(t1, __fmul_rn(2.0f, dot));
                    unsigned int e = __float_as_uint(d);
                    e = (e & 0x80000000u) ? ~e : (e | 0x80000000u);
                    unsigned long long pk =
                        ((unsigned long long)e << 32) | (unsigned int)(nt0 + n);
                    if (pk < bestpk) bestpk = pk;
                }
            }
            atomicMin(&g_best[token], bestpk);
        }
    }
}

// ---------------- extract indices, bump counts ----------------
__global__ void post_idx(float* __restrict__ out) {
    int n = blockIdx.x * blockDim.x + threadIdx.x;
    if (n >= NTOK) return;
    unsigned long long pk = g_best[n];
    int id = (int)(pk & 0xFFFFFFFFull);
    g_idx[n] = id;
    out[OUT_IDX + n] = (float)id;
    atomicAdd(&g_counts[id], 1.0f);
}

// ---------------- quantized output + commitment loss (coalesced) ----------------
// grid (DIM, 32): block = (c, b); 256 threads x 4 iters over hw.
__global__ void quant_loss(const float* __restrict__ x,
                           const float* __restrict__ cb,
                           float* __restrict__ out) {
    int c = blockIdx.x, b = blockIdx.y;
    int tid = threadIdx.x, lane = tid & 31;
    float ls = 0.0f;
    #pragma unroll
    for (int it = 0; it < 4; it++) {
        int hw = it * 256 + tid;
        int n  = (b << 10) + hw;
        int id = g_idx[n];
        float qv = __ldg(cb + (size_t)id * DIM + c);
        size_t off = (size_t)b * DIM * HW + (size_t)c * HW + hw;
        float xv = x[off];
        out[OUT_Q + off] = __fadd_rn(xv, __fsub_rn(qv, xv));
        float d = __fsub_rn(qv, xv);
        ls = fmaf(d, d, ls);
    }
    double ds = (double)ls;
    #pragma unroll
    for (int o = 16; o; o >>= 1) ds += __shfl_down_sync(0xFFFFFFFFu, ds, o);
    if (lane == 0) atomicAdd(&g_loss, ds);
}

// ---------------- dw = segment_sum(flat, idx) ----------------
__global__ void dw_kernel(const float* __restrict__ x) {
    int n = blockIdx.x * blockDim.x + threadIdx.x;
    int d = blockIdx.y;
    int b = n >> 10, hw = n & 1023;
    float v = x[(size_t)b * DIM * HW + (size_t)d * HW + hw];
    atomicAdd(&g_dw[(size_t)g_idx[n] * DIM + d], v);
}

// ---------------- EMA finalize ----------------
__global__ void final_kernel(const float* __restrict__ ema_count,
                             const float* __restrict__ ema_weight,
                             float* __restrict__ out) {
    int k = blockIdx.x;
    int c = threadIdx.x;
    float nc = ema_count[k] * 0.95f + 0.05f * g_counts[k];
    const float denom = (float)(32768.0 + 8192.0 * 1e-5);
    nc = (nc + 1e-5f) / denom * 32768.0f;
    float w = ema_weight[(size_t)k * DIM + c] * 0.95f + 0.05f * g_dw[(size_t)k * DIM + c];
    out[OUT_W  + (size_t)k * DIM + c] = w;
    out[OUT_CB + (size_t)k * DIM + c] = w / nc;
    if (c == 0) out[OUT_CNT + k] = nc;
    if (k == 0 && c == 0) {
        double mean = g_loss / (double)((size_t)NTOK * DIM);
        out[OUT_LOSS] = 0.25f * (float)mean;
    }
}

extern "C" void kernel_launch(void* const* d_in, const int* in_sizes, int n_in,
                              void* d_out, int out_size) {
    const float* x          = (const float*)d_in[0];
    const float* cb         = (const float*)d_in[1];
    const float* ema_count  = (const float*)d_in[2];
    const float* ema_weight = (const float*)d_in[3];
    float* out = (float*)d_out;

    static int smem_set = 0;
    if (!smem_set) {
        cudaFuncSetAttribute(gemm_argmin_tc,
                             cudaFuncAttributeMaxDynamicSharedMemorySize, SMEM_B);
        smem_set = 1;
    }

    init_kernel<<<(K_CODES * DIM + 255) / 256, 256>>>();
    decomp_x<<<NTOK * DIM / 4 / 256, 256>>>((const float4*)x);
    decomp_cbT<<<dim3(K_CODES / 32, DIM / 32), dim3(32, 32)>>>(cb);
    znorm_kernel<<<NTOK / 4 / 128, 128>>>(x);
    cbnorm_kernel<<<(K_CODES * 32 + 255) / 256, 256>>>(cb);
    gemm_argmin_tc<<<dim3(K_CODES / 128, NTOK / 128), 256, SMEM_B>>>();
    post_idx<<<NTOK / 256, 256>>>(out);
    quant_loss<<<dim3(DIM, 32), 256>>>(x, cb, out);
    dw_kernel<<<dim3(NTOK / 256, DIM), 256>>>(x);
    final_kernel<<<K_CODES, DIM>>>(ema_count, ema_weight, out);
}

// round 12
// speedup vs baseline: 1.7368x; 1.5528x over previous
#include <cuda_runtime.h>
#include <stdint.h>
#include <math_constants.h>

#define K_CODES 8192
#define DIM     256
#define NTOK    32768
#define HW      1024

// output layout (floats): loss | quantized | indices | new_count | new_weight | new_codebook
#define OUT_LOSS 0
#define OUT_Q    1
#define OUT_IDX  (OUT_Q  + 32*DIM*HW)
#define OUT_CNT  (OUT_IDX + NTOK)
#define OUT_W    (OUT_CNT + K_CODES)
#define OUT_CB   (OUT_W   + K_CODES*DIM)

#define WINDOW 3.0e-4f   // sound candidate window (see analysis)

// ---------------- device scratch ----------------
__device__ __align__(128) float g_xhi[NTOK * DIM];      // tf32(x), layout [b][d][hw]
__device__ __align__(128) float g_cbhiT[DIM * K_CODES]; // tf32(cb) transposed [d][code]
__device__ __align__(128) float g_dhh[(size_t)NTOK * K_CODES]; // screening distances
__device__ float  g_cbnorm[K_CODES];
__device__ float  g_znorm[NTOK];
__device__ double g_zpart[4][NTOK];
__device__ float  g_counts[K_CODES];
__device__ float  g_dw[K_CODES * DIM];
__device__ double g_loss;
__device__ int    g_idx[NTOK];

__device__ __forceinline__ uint32_t smem_u32(const void* p) {
    uint32_t a;
    asm("{ .reg .u64 t; cvta.to.shared.u64 t, %1; cvt.u32.u64 %0, t; }" : "=r"(a) : "l"(p));
    return a;
}
__device__ __forceinline__ float to_tf32(float v) {
    uint32_t u;
    asm("cvt.rna.satfinite.tf32.f32 %0, %1;" : "=r"(u) : "f"(v));
    return __uint_as_float(u);
}
#define CP16(dst, src) \
    asm volatile("cp.async.ca.shared.global [%0], [%1], 16;" :: "r"(dst), "l"(src))
#define CP_COMMIT() asm volatile("cp.async.commit_group;" ::: "memory")
#define CP_WAIT0()  asm volatile("cp.async.wait_group 0;" ::: "memory")

#define MMA_TF32(c, a, b) \
    asm volatile("mma.sync.aligned.m16n8k8.row.col.f32.tf32.tf32.f32 " \
        "{%0,%1,%2,%3}, {%4,%5,%6,%7}, {%8,%9}, {%0,%1,%2,%3};" \
        : "+f"((c)[0]), "+f"((c)[1]), "+f"((c)[2]), "+f"((c)[3]) \
        : "r"((a)[0]), "r"((a)[1]), "r"((a)[2]), "r"((a)[3]), "r"((b)[0]), "r"((b)[1]))

// ---------------- init ----------------
__global__ void init_kernel() {
    int i = blockIdx.x * blockDim.x + threadIdx.x;
    if (i < K_CODES * DIM) g_dw[i] = 0.0f;
    if (i < K_CODES)       g_counts[i] = 0.0f;
    if (i == 0)            g_loss = 0.0;
}

// ---------------- decompose x -> tf32 hi (float4) ----------------
__global__ void decomp_x(const float4* __restrict__ x4) {
    int i = blockIdx.x * blockDim.x + threadIdx.x;
    float4 v = x4[i];
    float4 hi;
    hi.x = to_tf32(v.x); hi.y = to_tf32(v.y);
    hi.z = to_tf32(v.z); hi.w = to_tf32(v.w);
    ((float4*)g_xhi)[i] = hi;
}

// ---------------- decompose + transpose codebook -> [d][code] hi ----------------
__global__ void decomp_cbT(const float* __restrict__ cb) {
    __shared__ float tile[32][33];
    int tx = threadIdx.x, ty = threadIdx.y;
    int c0 = blockIdx.x * 32, d0 = blockIdx.y * 32;
    tile[ty][tx] = cb[(size_t)(c0 + ty) * DIM + d0 + tx];
    __syncthreads();
    float v = tile[tx][ty];                  // code = c0+tx, d = d0+ty
    g_cbhiT[(size_t)(d0 + ty) * K_CODES + c0 + tx] = to_tf32(v);
}

// ---------------- token norm partials: 4 tokens/thread (float4), 64 d's/chunk ----
__global__ void znorm_part(const float* __restrict__ x) {
    int t4 = blockIdx.x * blockDim.x + threadIdx.x;     // 0..8191
    int chunk = blockIdx.y;                             // 0..3
    int b   = t4 >> 8;
    int hw4 = t4 & 255;
    const float4* p = (const float4*)(x + (size_t)b * DIM * HW
                                      + (size_t)(chunk * 64) * HW) + hw4;
    double s0 = 0.0, s1 = 0.0, s2 = 0.0, s3 = 0.0;
    #pragma unroll 8
    for (int d = 0; d < 64; d++) {
        float4 v = p[(size_t)d * 256];
        double vx = (double)v.x, vy = (double)v.y, vz = (double)v.z, vw = (double)v.w;
        s0 = fma(vx, vx, s0);
        s1 = fma(vy, vy, s1);
        s2 = fma(vz, vz, s2);
        s3 = fma(vw, vw, s3);
    }
    int token = (b << 10) + hw4 * 4;
    g_zpart[chunk][token + 0] = s0;
    g_zpart[chunk][token + 1] = s1;
    g_zpart[chunk][token + 2] = s2;
    g_zpart[chunk][token + 3] = s3;
}
__global__ void znorm_comb() {
    int token = blockIdx.x * blockDim.x + threadIdx.x;
    g_znorm[token] = (float)((g_zpart[0][token] + g_zpart[1][token])
                           + (g_zpart[2][token] + g_zpart[3][token]));
}

// ---------------- codebook norms (fp64 -> fp32) ----------------
__global__ void cbnorm_kernel(const float* __restrict__ cb) {
    int gt = blockIdx.x * blockDim.x + threadIdx.x;
    int code = gt >> 5, lane = gt & 31;
    if (code >= K_CODES) return;
    const float* r = cb + (size_t)code * DIM;
    double s = 0.0;
    #pragma unroll
    for (int i = lane; i < DIM; i += 32) {
        double v = (double)__ldg(r + i);
        s = fma(v, v, s);
    }
    #pragma unroll
    for (int o = 16; o; o >>= 1) s += __shfl_down_sync(0xFFFFFFFFu, s, o);
    if (lane == 0) g_cbnorm[code] = (float)s;
}

// ---------------- screening GEMM: hh-only tf32 mma, writes d_scan ----------------
// grid (64, 256): 128 codes x 128 tokens per CTA; BK=16, 2-stage cp.async.
#define ROWP    136
#define NKROW   16
#define ARR_F   (NKROW * ROWP)       // 2176 floats
#define STAGE_F (2 * ARR_F)          // A + B per stage = 4352 floats
#define NKSTEP  16
#define EPI_P   132                  // epilogue tile row pitch (floats)
#define SMEM_B  (128 * EPI_P * 4)    // 67584 B >= pipeline's 34816 B

__global__ void __launch_bounds__(256, 2)
screen_gemm(void) {
    extern __shared__ float smf[];
    const uint32_t smb = smem_u32(smf);

    const int tid  = threadIdx.x;
    const int lane = tid & 31;
    const int wid  = tid >> 5;
    const int g    = lane >> 2;
    const int q    = lane & 3;

    const int tb  = blockIdx.y;
    const int ct  = blockIdx.x;
    const int b   = (tb * 128) >> 10;
    const int hw0 = (tb * 128) & 1023;
    const int nt0 = ct * 128;

    const int mbase = (wid & 3) * 32;
    const int nbase = (wid >> 2) * 64;

    float acc[2][8][4];
    #pragma unroll
    for (int mf = 0; mf < 2; mf++)
        #pragma unroll
        for (int nf = 0; nf < 8; nf++)
            #pragma unroll
            for (int c = 0; c < 4; c++) acc[mf][nf][c] = 0.0f;

    auto issue = [&](int s, int k0) {
        const float* ap = g_xhi + ((size_t)(b * DIM + k0) << 10) + hw0;
        const float* bp = g_cbhiT + ((size_t)k0 << 13) + nt0;
        #pragma unroll
        for (int i = 0; i < 2; i++) {
            int idx = i * 256 + tid;
            int row = idx >> 5;
            int seg = (idx & 31) * 4;
            CP16(smb + 4u * (s * STAGE_F + row * ROWP + seg),
                 ap + (size_t)row * 1024 + seg);
            CP16(smb + 4u * (s * STAGE_F + ARR_F + row * ROWP + seg),
                 bp + (size_t)row * 8192 + seg);
        }
        CP_COMMIT();
    };

    issue(0, 0);

    #pragma unroll 1
    for (int ks = 0; ks < NKSTEP; ks++) {
        CP_WAIT0();
        __syncthreads();
        if (ks < NKSTEP - 1) issue((ks + 1) & 1, (ks + 1) * NKROW);

        const uint32_t* Ah = (const uint32_t*)(smf + (ks & 1) * STAGE_F);
        const uint32_t* Bh = Ah + ARR_F;

        #pragma unroll
        for (int kk = 0; kk < 2; kk++) {
            const int r0 = kk * 8 + q;
            const int r1 = r0 + 4;
            uint32_t af[2][4], bf[8][2];
            #pragma unroll
            for (int mf = 0; mf < 2; mf++) {
                int m = mbase + mf * 16 + g;
                af[mf][0] = Ah[r0 * ROWP + m];
                af[mf][1] = Ah[r0 * ROWP + m + 8];
                af[mf][2] = Ah[r1 * ROWP + m];
                af[mf][3] = Ah[r1 * ROWP + m + 8];
            }
            #pragma unroll
            for (int nf = 0; nf < 8; nf++) {
                int n = nbase + nf * 8 + g;
                bf[nf][0] = Bh[r0 * ROWP + n];
                bf[nf][1] = Bh[r1 * ROWP + n];
            }
            #pragma unroll
            for (int mf = 0; mf < 2; mf++)
                #pragma unroll
                for (int nf = 0; nf < 8; nf++)
                    MMA_TF32(acc[mf][nf], af[mf], bf[nf]);
        }
    }

    // epilogue: d_scan = cn - 2*dot_hh; stage in smem, store coalesced.
    __syncthreads();
    #pragma unroll
    for (int mf = 0; mf < 2; mf++)
        #pragma unroll
        for (int h = 0; h < 2; h++) {
            int m = mbase + mf * 16 + g + h * 8;
            #pragma unroll
            for (int nf = 0; nf < 8; nf++) {
                int n = nbase + nf * 8 + q * 2;
                float2 w;
                w.x = fmaf(-2.0f, acc[mf][nf][h * 2 + 0], __ldg(&g_cbnorm[nt0 + n]));
                w.y = fmaf(-2.0f, acc[mf][nf][h * 2 + 1], __ldg(&g_cbnorm[nt0 + n + 1]));
                *(float2*)&smf[m * EPI_P + n] = w;
            }
        }
    __syncthreads();
    float* drow = g_dhh + (size_t)(tb * 128) * K_CODES + nt0;
    #pragma unroll
    for (int i = 0; i < 16; i++) {
        int f = i * 256 + tid;           // 0..4095 float4 slots
        int row = f >> 5;
        int c4  = (f & 31) * 4;
        float4 v = *(float4*)&smf[row * EPI_P + c4];
        *(float4*)(drow + (size_t)row * K_CODES + c4) = v;
    }
}

// ---------------- scan + rescore: one block per token ----------------
#define MAXCAND 512
__global__ void __launch_bounds__(256, 4)
scan_rescore(const float* __restrict__ x, const float* __restrict__ cb,
             float* __restrict__ out) {
    __shared__ float swmin[8];
    __shared__ int   scnt;
    __shared__ int   scand[MAXCAND];
    __shared__ unsigned long long sbest;

    const int t = blockIdx.x;
    const int tid = threadIdx.x, lane = tid & 31, wid = tid >> 5;

    const float4* rowp = (const float4*)(g_dhh + (size_t)t * K_CODES);
    float vals[32];
    float lmin = CUDART_INF_F;
    #pragma unroll
    for (int i = 0; i < 8; i++) {
        float4 v = rowp[i * 256 + tid];
        vals[i * 4 + 0] = v.x; vals[i * 4 + 1] = v.y;
        vals[i * 4 + 2] = v.z; vals[i * 4 + 3] = v.w;
        lmin = fminf(lmin, fminf(fminf(v.x, v.y), fminf(v.z, v.w)));
    }
    #pragma unroll
    for (int o = 16; o; o >>= 1) lmin = fminf(lmin, __shfl_down_sync(0xFFFFFFFFu, lmin, o));
    if (lane == 0) swmin[wid] = lmin;
    if (tid == 0) { scnt = 0; sbest = 0xFFFFFFFFFFFFFFFFull; }
    __syncthreads();
    float dmin = swmin[0];
    #pragma unroll
    for (int w = 1; w < 8; w++) dmin = fminf(dmin, swmin[w]);
    const float thr = dmin + WINDOW;

    #pragma unroll
    for (int i = 0; i < 8; i++)
        #pragma unroll
        for (int j = 0; j < 4; j++)
            if (vals[i * 4 + j] <= thr) {
                int pos = atomicAdd(&scnt, 1);
                if (pos < MAXCAND) scand[pos] = (i * 256 + tid) * 4 + j;
            }
    __syncthreads();
    int ncand = min(scnt, MAXCAND);

    const int b = t >> 10, hw = t & 1023;
    const float* xbase = x + (size_t)b * DIM * HW + hw;
    const float zn = g_znorm[t];

    for (int j = wid; j < ncand; j += 8) {
        int c = scand[j];
        const float* crow = cb + (size_t)c * DIM;
        double s = 0.0;
        #pragma unroll
        for (int i = 0; i < 8; i++) {
            int d = lane + i * 32;
            double xv = (double)__ldg(xbase + (size_t)d * HW);
            double cv = (double)__ldg(crow + d);
            s = fma(xv, cv, s);
        }
        #pragma unroll
        for (int o = 16; o; o >>= 1) s += __shfl_down_sync(0xFFFFFFFFu, s, o);
        if (lane == 0) {
            float dotf = (float)s;
            float t1 = __fadd_rn(zn, __ldg(&g_cbnorm[c]));
            float d  = __fsub_rn(t1, __fmul_rn(2.0f, dotf));
            unsigned int e = __float_as_uint(d);
            e = (e & 0x80000000u) ? ~e : (e | 0x80000000u);
            atomicMin(&sbest, ((unsigned long long)e << 32) | (unsigned int)c);
        }
    }
    __syncthreads();
    if (tid == 0) {
        int id = (int)(sbest & 0xFFFFFFFFull);
        g_idx[t] = id;
        out[OUT_IDX + t] = (float)id;
        atomicAdd(&g_counts[id], 1.0f);
    }
}

// ---------------- quantized output + commitment loss (coalesced) ----------------
__global__ void quant_loss(const float* __restrict__ x,
                           const float* __restrict__ cb,
                           float* __restrict__ out) {
    int c = blockIdx.x, b = blockIdx.y;
    int tid = threadIdx.x, lane = tid & 31;
    float ls = 0.0f;
    #pragma unroll
    for (int it = 0; it < 4; it++) {
        int hw = it * 256 + tid;
        int n  = (b << 10) + hw;
        int id = g_idx[n];
        float qv = __ldg(cb + (size_t)id * DIM + c);
        size_t off = (size_t)b * DIM * HW + (size_t)c * HW + hw;
        float xv = x[off];
        out[OUT_Q + off] = __fadd_rn(xv, __fsub_rn(qv, xv));
        float d = __fsub_rn(qv, xv);
        ls = fmaf(d, d, ls);
    }
    double ds = (double)ls;
    #pragma unroll
    for (int o = 16; o; o >>= 1) ds += __shfl_down_sync(0xFFFFFFFFu, ds, o);
    if (lane == 0) atomicAdd(&g_loss, ds);
}

// ---------------- dw = segment_sum(flat, idx) ----------------
__global__ void dw_kernel(const float* __restrict__ x) {
    int n = blockIdx.x * blockDim.x + threadIdx.x;
    int d = blockIdx.y;
    int b = n >> 10, hw = n & 1023;
    float v = x[(size_t)b * DIM * HW + (size_t)d * HW + hw];
    atomicAdd(&g_dw[(size_t)g_idx[n] * DIM + d], v);
}

// ---------------- EMA finalize ----------------
__global__ void final_kernel(const float* __restrict__ ema_count,
                             const float* __restrict__ ema_weight,
                             float* __restrict__ out) {
    int k = blockIdx.x;
    int c = threadIdx.x;
    float nc = ema_count[k] * 0.95f + 0.05f * g_counts[k];
    const float denom = (float)(32768.0 + 8192.0 * 1e-5);
    nc = (nc + 1e-5f) / denom * 32768.0f;
    float w = ema_weight[(size_t)k * DIM + c] * 0.95f + 0.05f * g_dw[(size_t)k * DIM + c];
    out[OUT_W  + (size_t)k * DIM + c] = w;
    out[OUT_CB + (size_t)k * DIM + c] = w / nc;
    if (c == 0) out[OUT_CNT + k] = nc;
    if (k == 0 && c == 0) {
        double mean = g_loss / (double)((size_t)NTOK * DIM);
        out[OUT_LOSS] = 0.25f * (float)mean;
    }
}

extern "C" void kernel_launch(void* const* d_in, const int* in_sizes, int n_in,
                              void* d_out, int out_size) {
    const float* x          = (const float*)d_in[0];
    const float* cb         = (const float*)d_in[1];
    const float* ema_count  = (const float*)d_in[2];
    const float* ema_weight = (const float*)d_in[3];
    float* out = (float*)d_out;

    static int smem_set = 0;
    if (!smem_set) {
        cudaFuncSetAttribute(screen_gemm,
                             cudaFuncAttributeMaxDynamicSharedMemorySize, SMEM_B);
        smem_set = 1;
    }

    init_kernel<<<(K_CODES * DIM + 255) / 256, 256>>>();
    decomp_x<<<NTOK * DIM / 4 / 256, 256>>>((const float4*)x);
    decomp_cbT<<<dim3(K_CODES / 32, DIM / 32), dim3(32, 32)>>>(cb);
    znorm_part<<<dim3(NTOK / 4 / 256, 4), 256>>>(x);
    znorm_comb<<<NTOK / 256, 256>>>();
    cbnorm_kernel<<<(K_CODES * 32 + 255) / 256, 256>>>(cb);
    screen_gemm<<<dim3(K_CODES / 128, NTOK / 128), 256, SMEM_B>>>();
    scan_rescore<<<NTOK, 256>>>(x, cb, out);
    quant_loss<<<dim3(DIM, 32), 256>>>(x, cb, out);
    dw_kernel<<<dim3(NTOK / 256, DIM), 256>>>(x);
    final_kernel<<<K_CODES, DIM>>>(ema_count, ema_weight, out);
}

// round 13
// speedup vs baseline: 2.4079x; 1.3864x over previous
#include <cuda_runtime.h>
#include <cuda_fp16.h>
#include <stdint.h>
#include <math_constants.h>

#define K_CODES 8192
#define DIM     256
#define NTOK    32768
#define HW      1024

// output layout (floats): loss | quantized | indices | new_count | new_weight | new_codebook
#define OUT_LOSS 0
#define OUT_Q    1
#define OUT_IDX  (OUT_Q  + 32*DIM*HW)
#define OUT_CNT  (OUT_IDX + NTOK)
#define OUT_W    (OUT_CNT + K_CODES)
#define OUT_CB   (OUT_W   + K_CODES*DIM)

#define WINDOW 3.0e-4f   // sound candidate window (fp16 screening: need 1.5e-4)

// ---------------- device scratch ----------------
__device__ __align__(128) __half g_x16T[NTOK * DIM];     // half(x), [token][d]
__device__ __align__(128) __half g_cb16[K_CODES * DIM];  // half(cb * 2^13), [code][d]
__device__ __align__(128) __half g_dhh16[(size_t)NTOK * K_CODES]; // fp16 d_scan
__device__ float  g_cbnorm[K_CODES];
__device__ float  g_znorm[NTOK];
__device__ double g_zpart[4][NTOK];
__device__ float  g_counts[K_CODES];
__device__ float  g_dw[K_CODES * DIM];
__device__ double g_loss;
__device__ int    g_idx[NTOK];

__device__ __forceinline__ uint32_t smem_u32(const void* p) {
    uint32_t a;
    asm("{ .reg .u64 t; cvta.to.shared.u64 t, %1; cvt.u32.u64 %0, t; }" : "=r"(a) : "l"(p));
    return a;
}
#define CP16(dst, src) \
    asm volatile("cp.async.ca.shared.global [%0], [%1], 16;" :: "r"(dst), "l"(src))
#define CP_COMMIT() asm volatile("cp.async.commit_group;" ::: "memory")
#define CP_WAIT0()  asm volatile("cp.async.wait_group 0;" ::: "memory")

#define MMA_F16(c, a, b) \
    asm volatile("mma.sync.aligned.m16n8k16.row.col.f32.f16.f16.f32 " \
        "{%0,%1,%2,%3}, {%4,%5,%6,%7}, {%8,%9}, {%0,%1,%2,%3};" \
        : "+f"((c)[0]), "+f"((c)[1]), "+f"((c)[2]), "+f"((c)[3]) \
        : "r"((a)[0]), "r"((a)[1]), "r"((a)[2]), "r"((a)[3]), "r"((b)[0]), "r"((b)[1]))

// ---------------- init ----------------
__global__ void init_kernel() {
    int i = blockIdx.x * blockDim.x + threadIdx.x;
    if (i < K_CODES * DIM) g_dw[i] = 0.0f;
    if (i < K_CODES)       g_counts[i] = 0.0f;
    if (i == 0)            g_loss = 0.0;
}

// ---------------- x -> half, transposed to [token][d] ----------------
__global__ void decomp_x16T(const float* __restrict__ x) {
    __shared__ float tile[32][33];
    int tx = threadIdx.x, ty = threadIdx.y;
    int hw0 = blockIdx.x * 32, d0 = blockIdx.y * 32, b = blockIdx.z;
    tile[ty][tx] = x[(size_t)b * DIM * HW + (size_t)(d0 + ty) * HW + hw0 + tx];
    __syncthreads();
    // token = b*1024 + hw0 + ty, d = d0 + tx
    g_x16T[(size_t)(b * 1024 + hw0 + ty) * DIM + d0 + tx] = __float2half_rn(tile[tx][ty]);
}

// ---------------- cb -> half(cb * 2^13), [code][d] ----------------
__global__ void decomp_cb16(const float* __restrict__ cb) {
    int i = blockIdx.x * blockDim.x + threadIdx.x;
    g_cb16[i] = __float2half_rn(cb[i] * 8192.0f);
}

// ---------------- token norm partials (fp64), 4 tokens/thread, 64 d's/chunk ----
__global__ void znorm_part(const float* __restrict__ x) {
    int t4 = blockIdx.x * blockDim.x + threadIdx.x;
    int chunk = blockIdx.y;
    int b   = t4 >> 8;
    int hw4 = t4 & 255;
    const float4* p = (const float4*)(x + (size_t)b * DIM * HW
                                      + (size_t)(chunk * 64) * HW) + hw4;
    double s0 = 0.0, s1 = 0.0, s2 = 0.0, s3 = 0.0;
    #pragma unroll 8
    for (int d = 0; d < 64; d++) {
        float4 v = p[(size_t)d * 256];
        double vx = (double)v.x, vy = (double)v.y, vz = (double)v.z, vw = (double)v.w;
        s0 = fma(vx, vx, s0);
        s1 = fma(vy, vy, s1);
        s2 = fma(vz, vz, s2);
        s3 = fma(vw, vw, s3);
    }
    int token = (b << 10) + hw4 * 4;
    g_zpart[chunk][token + 0] = s0;
    g_zpart[chunk][token + 1] = s1;
    g_zpart[chunk][token + 2] = s2;
    g_zpart[chunk][token + 3] = s3;
}
__global__ void znorm_comb() {
    int token = blockIdx.x * blockDim.x + threadIdx.x;
    g_znorm[token] = (float)((g_zpart[0][token] + g_zpart[1][token])
                           + (g_zpart[2][token] + g_zpart[3][token]));
}

// ---------------- codebook norms (fp64 -> fp32) ----------------
__global__ void cbnorm_kernel(const float* __restrict__ cb) {
    int gt = blockIdx.x * blockDim.x + threadIdx.x;
    int code = gt >> 5, lane = gt & 31;
    if (code >= K_CODES) return;
    const float* r = cb + (size_t)code * DIM;
    double s = 0.0;
    #pragma unroll
    for (int i = lane; i < DIM; i += 32) {
        double v = (double)__ldg(r + i);
        s = fma(v, v, s);
    }
    #pragma unroll
    for (int o = 16; o; o >>= 1) s += __shfl_down_sync(0xFFFFFFFFu, s, o);
    if (lane == 0) g_cbnorm[code] = (float)s;
}

// ---------------- fp16 screening GEMM: d_scan = cn - 2^-12 * dot_scaled ----------
// grid (64, 256): 128 codes x 128 tokens per CTA; BK=32 halves, 2-stage cp.async.
#define AP      40                    // smem row pitch (halves)
#define TILE_H  (128 * AP)            // one array (A or B) = 5120 halves
#define STAGE_H (2 * TILE_H)          // 10240 halves = 20480 B
#define NKSTEP  8
#define EPI_P   136                   // epilogue pitch (halves)
#define SMEM_B  (2 * STAGE_H * 2)     // 40960 B (>= epilogue 34816 B)

__global__ void __launch_bounds__(256, 2)
screen_gemm16(void) {
    extern __shared__ __half smh[];
    const uint32_t smb = smem_u32(smh);

    const int tid  = threadIdx.x;
    const int lane = tid & 31;
    const int wid  = tid >> 5;
    const int g    = lane >> 2;
    const int q    = lane & 3;

    const int tb  = blockIdx.y;
    const int ct  = blockIdx.x;
    const int nt0 = ct * 128;

    const int mbase = (wid & 3) * 32;
    const int nbase = (wid >> 2) * 64;

    float acc[2][8][4];
    #pragma unroll
    for (int mf = 0; mf < 2; mf++)
        #pragma unroll
        for (int nf = 0; nf < 8; nf++)
            #pragma unroll
            for (int c = 0; c < 4; c++) acc[mf][nf][c] = 0.0f;

    // stage: A rows = tokens (tb*128+row), B rows = codes (nt0+row); 32 halves/row.
    auto issue = [&](int s, int k0) {
        const __half* ap = g_x16T + (size_t)(tb * 128) * DIM + k0;
        const __half* bp = g_cb16 + (size_t)nt0 * DIM + k0;
        #pragma unroll
        for (int i = 0; i < 2; i++) {
            int idx = i * 256 + tid;        // 0..511
            int row = idx >> 2;             // 0..127
            int seg = idx & 3;              // 16B segments of the 64B row
            CP16(smb + 2u * (s * STAGE_H + row * AP + seg * 8),
                 ap + (size_t)row * DIM + seg * 8);
            CP16(smb + 2u * (s * STAGE_H + TILE_H + row * AP + seg * 8),
                 bp + (size_t)row * DIM + seg * 8);
        }
        CP_COMMIT();
    };

    issue(0, 0);

    #pragma unroll 1
    for (int ks = 0; ks < NKSTEP; ks++) {
        CP_WAIT0();
        __syncthreads();
        if (ks < NKSTEP - 1) issue((ks + 1) & 1, (ks + 1) * 32);

        const uint32_t* A32 = (const uint32_t*)(smh + (ks & 1) * STAGE_H);
        const uint32_t* B32 = A32 + TILE_H / 2;

        #pragma unroll
        for (int kl2 = 0; kl2 < 2; kl2++) {     // two k16 sub-steps per stage
            const int klh = kl2 * 8;            // uint32 offset (16 halves)
            uint32_t af[2][4], bf[8][2];
            #pragma unroll
            for (int mf = 0; mf < 2; mf++) {
                int m = mbase + mf * 16 + g;
                af[mf][0] = A32[m * (AP / 2) + klh + q];
                af[mf][1] = A32[(m + 8) * (AP / 2) + klh + q];
                af[mf][2] = A32[m * (AP / 2) + klh + 4 + q];
                af[mf][3] = A32[(m + 8) * (AP / 2) + klh + 4 + q];
            }
            #pragma unroll
            for (int nf = 0; nf < 8; nf++) {
                int n = nbase + nf * 8 + g;
                bf[nf][0] = B32[n * (AP / 2) + klh + q];
                bf[nf][1] = B32[n * (AP / 2) + klh + 4 + q];
            }
            #pragma unroll
            for (int mf = 0; mf < 2; mf++)
                #pragma unroll
                for (int nf = 0; nf < 8; nf++)
                    MMA_F16(acc[mf][nf], af[mf], bf[nf]);
        }
    }

    // epilogue: d_scan = fmaf(-2^-12, dot_scaled, cn); stage in smem, store coalesced.
    __syncthreads();
    #pragma unroll
    for (int mf = 0; mf < 2; mf++)
        #pragma unroll
        for (int h = 0; h < 2; h++) {
            int m = mbase + mf * 16 + g + h * 8;
            #pragma unroll
            for (int nf = 0; nf < 8; nf++) {
                int n = nbase + nf * 8 + q * 2;
                float d0 = fmaf(-0.000244140625f, acc[mf][nf][h * 2 + 0],
                                __ldg(&g_cbnorm[nt0 + n]));
                float d1 = fmaf(-0.000244140625f, acc[mf][nf][h * 2 + 1],
                                __ldg(&g_cbnorm[nt0 + n + 1]));
                *(__half2*)&smh[m * EPI_P + n] = __floats2half2_rn(d0, d1);
            }
        }
    __syncthreads();
    __half* drow = g_dhh16 + (size_t)(tb * 128) * K_CODES + nt0;
    #pragma unroll
    for (int i = 0; i < 8; i++) {
        int idx = i * 256 + tid;            // 0..2047 uint4 chunks
        int row = idx >> 4;
        int ch  = idx & 15;
        uint4 v = *(const uint4*)&smh[row * EPI_P + ch * 8];
        *(uint4*)(drow + (size_t)row * K_CODES + ch * 8) = v;
    }
}

// ---------------- scan + rescore: one block per token ----------------
#define MAXCAND 512
__global__ void __launch_bounds__(256, 4)
scan_rescore(const float* __restrict__ x, const float* __restrict__ cb,
             float* __restrict__ out) {
    __shared__ float swmin[8];
    __shared__ int   scnt;
    __shared__ int   scand[MAXCAND];
    __shared__ unsigned long long sbest;

    const int t = blockIdx.x;
    const int tid = threadIdx.x, lane = tid & 31, wid = tid >> 5;

    const uint4* rowp = (const uint4*)(g_dhh16 + (size_t)t * K_CODES);
    float vals[32];
    float lmin = CUDART_INF_F;
    #pragma unroll
    for (int i = 0; i < 4; i++) {
        uint4 v = rowp[i * 256 + tid];
        const uint32_t w[4] = {v.x, v.y, v.z, v.w};
        #pragma unroll
        for (int j = 0; j < 4; j++) {
            float2 f = __half22float2(*(const __half2*)&w[j]);
            vals[i * 8 + j * 2 + 0] = f.x;
            vals[i * 8 + j * 2 + 1] = f.y;
            lmin = fminf(lmin, fminf(f.x, f.y));
        }
    }
    #pragma unroll
    for (int o = 16; o; o >>= 1) lmin = fminf(lmin, __shfl_down_sync(0xFFFFFFFFu, lmin, o));
    if (lane == 0) swmin[wid] = lmin;
    if (tid == 0) { scnt = 0; sbest = 0xFFFFFFFFFFFFFFFFull; }
    __syncthreads();
    float dmin = swmin[0];
    #pragma unroll
    for (int w = 1; w < 8; w++) dmin = fminf(dmin, swmin[w]);
    const float thr = dmin + WINDOW;

    #pragma unroll
    for (int i = 0; i < 4; i++)
        #pragma unroll
        for (int j = 0; j < 8; j++)
            if (vals[i * 8 + j] <= thr) {
                int pos = atomicAdd(&scnt, 1);
                if (pos < MAXCAND) scand[pos] = (i * 256 + tid) * 8 + j;
            }
    __syncthreads();
    int ncand = min(scnt, MAXCAND);

    const int b = t >> 10, hw = t & 1023;
    const float* xbase = x + (size_t)b * DIM * HW + hw;
    const float zn = g_znorm[t];

    for (int j = wid; j < ncand; j += 8) {
        int c = scand[j];
        const float* crow = cb + (size_t)c * DIM;
        double s = 0.0;
        #pragma unroll
        for (int i = 0; i < 8; i++) {
            int d = lane + i * 32;
            double xv = (double)__ldg(xbase + (size_t)d * HW);
            double cv = (double)__ldg(crow + d);
            s = fma(xv, cv, s);
        }
        #pragma unroll
        for (int o = 16; o; o >>= 1) s += __shfl_down_sync(0xFFFFFFFFu, s, o);
        if (lane == 0) {
            float dotf = (float)s;
            float t1 = __fadd_rn(zn, __ldg(&g_cbnorm[c]));
            float d  = __fsub_rn(t1, __fmul_rn(2.0f, dotf));
            unsigned int e = __float_as_uint(d);
            e = (e & 0x80000000u) ? ~e : (e | 0x80000000u);
            atomicMin(&sbest, ((unsigned long long)e << 32) | (unsigned int)c);
        }
    }
    __syncthreads();
    if (tid == 0) {
        int id = (int)(sbest & 0xFFFFFFFFull);
        g_idx[t] = id;
        out[OUT_IDX + t] = (float)id;
        atomicAdd(&g_counts[id], 1.0f);
    }
}

// ---------------- quantized output + loss + dw (fused, coalesced) ----------------
__global__ void quant_loss_dw(const float* __restrict__ x,
                              const float* __restrict__ cb,
                              float* __restrict__ out) {
    int c = blockIdx.x, b = blockIdx.y;
    int tid = threadIdx.x, lane = tid & 31;
    float ls = 0.0f;
    #pragma unroll
    for (int it = 0; it < 4; it++) {
        int hw = it * 256 + tid;
        int n  = (b << 10) + hw;
        int id = g_idx[n];
        float qv = __ldg(cb + (size_t)id * DIM + c);
        size_t off = (size_t)b * DIM * HW + (size_t)c * HW + hw;
        float xv = x[off];
        out[OUT_Q + off] = __fadd_rn(xv, __fsub_rn(qv, xv));
        float d = __fsub_rn(qv, xv);
        ls = fmaf(d, d, ls);
        atomicAdd(&g_dw[(size_t)id * DIM + c], xv);
    }
    double ds = (double)ls;
    #pragma unroll
    for (int o = 16; o; o >>= 1) ds += __shfl_down_sync(0xFFFFFFFFu, ds, o);
    if (lane == 0) atomicAdd(&g_loss, ds);
}

// ---------------- EMA finalize ----------------
__global__ void final_kernel(const float* __restrict__ ema_count,
                             const float* __restrict__ ema_weight,
                             float* __restrict__ out) {
    int k = blockIdx.x;
    int c = threadIdx.x;
    float nc = ema_count[k] * 0.95f + 0.05f * g_counts[k];
    const float denom = (float)(32768.0 + 8192.0 * 1e-5);
    nc = (nc + 1e-5f) / denom * 32768.0f;
    float w = ema_weight[(size_t)k * DIM + c] * 0.95f + 0.05f * g_dw[(size_t)k * DIM + c];
    out[OUT_W  + (size_t)k * DIM + c] = w;
    out[OUT_CB + (size_t)k * DIM + c] = w / nc;
    if (c == 0) out[OUT_CNT + k] = nc;
    if (k == 0 && c == 0) {
        double mean = g_loss / (double)((size_t)NTOK * DIM);
        out[OUT_LOSS] = 0.25f * (float)mean;
    }
}

extern "C" void kernel_launch(void* const* d_in, const int* in_sizes, int n_in,
                              void* d_out, int out_size) {
    const float* x          = (const float*)d_in[0];
    const float* cb         = (const float*)d_in[1];
    const float* ema_count  = (const float*)d_in[2];
    const float* ema_weight = (const float*)d_in[3];
    float* out = (float*)d_out;

    static int smem_set = 0;
    if (!smem_set) {
        cudaFuncSetAttribute(screen_gemm16,
                             cudaFuncAttributeMaxDynamicSharedMemorySize, SMEM_B);
        smem_set = 1;
    }

    init_kernel<<<(K_CODES * DIM + 255) / 256, 256>>>();
    decomp_x16T<<<dim3(HW / 32, DIM / 32, 32), dim3(32, 32)>>>(x);
    decomp_cb16<<<K_CODES * DIM / 256, 256>>>(cb);
    znorm_part<<<dim3(NTOK / 4 / 256, 4), 256>>>(x);
    znorm_comb<<<NTOK / 256, 256>>>();
    cbnorm_kernel<<<(K_CODES * 32 + 255) / 256, 256>>>(cb);
    screen_gemm16<<<dim3(K_CODES / 128, NTOK / 128), 256, SMEM_B>>>();
    scan_rescore<<<NTOK, 256>>>(x, cb, out);
    quant_loss_dw<<<dim3(DIM, 32), 256>>>(x, cb, out);
    final_kernel<<<K_CODES, DIM>>>(ema_count, ema_weight, out);
}

// round 14
// speedup vs baseline: 2.5865x; 1.0742x over previous
#include <cuda_runtime.h>
#include <cuda_fp16.h>
#include <stdint.h>
#include <math_constants.h>

#define K_CODES 8192
#define DIM     256
#define NTOK    32768
#define HW      1024

// output layout (floats): loss | quantized | indices | new_count | new_weight | new_codebook
#define OUT_LOSS 0
#define OUT_Q    1
#define OUT_IDX  (OUT_Q  + 32*DIM*HW)
#define OUT_CNT  (OUT_IDX + NTOK)
#define OUT_W    (OUT_CNT + K_CODES)
#define OUT_CB   (OUT_W   + K_CODES*DIM)

#define WINDOW 3.0e-4f   // sound candidate window (fp16 screening: need 1.5e-4)
#define NTILE  (K_CODES / 128)   // 64 code tiles

// ---------------- device scratch ----------------
__device__ __align__(128) __half g_x16T[NTOK * DIM];     // half(x), [token][d]
__device__ __align__(128) __half g_cb16[K_CODES * DIM];  // half(cb * 2^13), [code][d]
__device__ __align__(128) __half g_dhh16[(size_t)NTOK * K_CODES]; // fp16 d_scan
__device__ __align__(128) float  g_tmin[NTILE * NTOK];   // [tile][token] tile minima
__device__ float  g_cbnorm[K_CODES];
__device__ float  g_znorm[NTOK];
__device__ double g_zpart[16][NTOK];
__device__ float  g_counts[K_CODES];
__device__ float  g_dw[K_CODES * DIM];
__device__ double g_loss;
__device__ int    g_idx[NTOK];

__device__ __forceinline__ uint32_t smem_u32(const void* p) {
    uint32_t a;
    asm("{ .reg .u64 t; cvta.to.shared.u64 t, %1; cvt.u32.u64 %0, t; }" : "=r"(a) : "l"(p));
    return a;
}
#define CP16(dst, src) \
    asm volatile("cp.async.ca.shared.global [%0], [%1], 16;" :: "r"(dst), "l"(src))
#define CP_COMMIT() asm volatile("cp.async.commit_group;" ::: "memory")
#define CP_WAIT0()  asm volatile("cp.async.wait_group 0;" ::: "memory")

#define MMA_F16(c, a, b) \
    asm volatile("mma.sync.aligned.m16n8k16.row.col.f32.f16.f16.f32 " \
        "{%0,%1,%2,%3}, {%4,%5,%6,%7}, {%8,%9}, {%0,%1,%2,%3};" \
        : "+f"((c)[0]), "+f"((c)[1]), "+f"((c)[2]), "+f"((c)[3]) \
        : "r"((a)[0]), "r"((a)[1]), "r"((a)[2]), "r"((a)[3]), "r"((b)[0]), "r"((b)[1]))

// ---------------- init ----------------
__global__ void init_kernel() {
    int i = blockIdx.x * blockDim.x + threadIdx.x;
    if (i < K_CODES * DIM) g_dw[i] = 0.0f;
    if (i < K_CODES)       g_counts[i] = 0.0f;
    if (i == 0)            g_loss = 0.0;
}

// ---------------- x -> half, transposed to [token][d] ----------------
__global__ void decomp_x16T(const float* __restrict__ x) {
    __shared__ float tile[32][33];
    int tx = threadIdx.x, ty = threadIdx.y;
    int hw0 = blockIdx.x * 32, d0 = blockIdx.y * 32, b = blockIdx.z;
    tile[ty][tx] = x[(size_t)b * DIM * HW + (size_t)(d0 + ty) * HW + hw0 + tx];
    __syncthreads();
    g_x16T[(size_t)(b * 1024 + hw0 + ty) * DIM + d0 + tx] = __float2half_rn(tile[tx][ty]);
}

// ---------------- cb -> half(cb * 2^13), [code][d] ----------------
__global__ void decomp_cb16(const float* __restrict__ cb) {
    int i = blockIdx.x * blockDim.x + threadIdx.x;
    g_cb16[i] = __float2half_rn(cb[i] * 8192.0f);
}

// ---------------- token norm partials (fp64), 16 chunks of 16 d's ----------------
__global__ void znorm_part(const float* __restrict__ x) {
    int t4 = blockIdx.x * blockDim.x + threadIdx.x;     // 0..8191
    int chunk = blockIdx.y;                             // 0..15
    int b   = t4 >> 8;
    int hw4 = t4 & 255;
    const float4* p = (const float4*)(x + (size_t)b * DIM * HW
                                      + (size_t)(chunk * 16) * HW) + hw4;
    double s0 = 0.0, s1 = 0.0, s2 = 0.0, s3 = 0.0;
    #pragma unroll
    for (int d = 0; d < 16; d++) {
        float4 v = p[(size_t)d * 256];
        double vx = (double)v.x, vy = (double)v.y, vz = (double)v.z, vw = (double)v.w;
        s0 = fma(vx, vx, s0);
        s1 = fma(vy, vy, s1);
        s2 = fma(vz, vz, s2);
        s3 = fma(vw, vw, s3);
    }
    int token = (b << 10) + hw4 * 4;
    g_zpart[chunk][token + 0] = s0;
    g_zpart[chunk][token + 1] = s1;
    g_zpart[chunk][token + 2] = s2;
    g_zpart[chunk][token + 3] = s3;
}
__global__ void znorm_comb() {
    int token = blockIdx.x * blockDim.x + threadIdx.x;
    double a0 = (g_zpart[0][token]  + g_zpart[1][token])
              + (g_zpart[2][token]  + g_zpart[3][token]);
    double a1 = (g_zpart[4][token]  + g_zpart[5][token])
              + (g_zpart[6][token]  + g_zpart[7][token]);
    double a2 = (g_zpart[8][token]  + g_zpart[9][token])
              + (g_zpart[10][token] + g_zpart[11][token]);
    double a3 = (g_zpart[12][token] + g_zpart[13][token])
              + (g_zpart[14][token] + g_zpart[15][token]);
    g_znorm[token] = (float)((a0 + a1) + (a2 + a3));
}

// ---------------- codebook norms (fp64 -> fp32) ----------------
__global__ void cbnorm_kernel(const float* __restrict__ cb) {
    int gt = blockIdx.x * blockDim.x + threadIdx.x;
    int code = gt >> 5, lane = gt & 31;
    if (code >= K_CODES) return;
    const float* r = cb + (size_t)code * DIM;
    double s = 0.0;
    #pragma unroll
    for (int i = lane; i < DIM; i += 32) {
        double v = (double)__ldg(r + i);
        s = fma(v, v, s);
    }
    #pragma unroll
    for (int o = 16; o; o >>= 1) s += __shfl_down_sync(0xFFFFFFFFu, s, o);
    if (lane == 0) g_cbnorm[code] = (float)s;
}

// ---------------- fp16 screening GEMM + per-tile minima ----------------
// grid (64, 256): 128 codes x 128 tokens per CTA; BK=32 halves, 2-stage cp.async.
#define AP      40                    // smem row pitch (halves)
#define TILE_H  (128 * AP)            // one array (A or B) = 5120 halves
#define STAGE_H (2 * TILE_H)          // 10240 halves = 20480 B
#define NKSTEP  8
#define EPI_P   136                   // epilogue pitch (halves)
#define SMEM_B  (2 * STAGE_H * 2)     // 40960 B (>= epilogue 34816 B)

__global__ void __launch_bounds__(256, 2)
screen_gemm16(void) {
    extern __shared__ __half smh[];
    const uint32_t smb = smem_u32(smh);

    const int tid  = threadIdx.x;
    const int lane = tid & 31;
    const int wid  = tid >> 5;
    const int g    = lane >> 2;
    const int q    = lane & 3;

    const int tb  = blockIdx.y;
    const int ct  = blockIdx.x;
    const int nt0 = ct * 128;

    const int mbase = (wid & 3) * 32;
    const int nbase = (wid >> 2) * 64;

    float acc[2][8][4];
    #pragma unroll
    for (int mf = 0; mf < 2; mf++)
        #pragma unroll
        for (int nf = 0; nf < 8; nf++)
            #pragma unroll
            for (int c = 0; c < 4; c++) acc[mf][nf][c] = 0.0f;

    auto issue = [&](int s, int k0) {
        const __half* ap = g_x16T + (size_t)(tb * 128) * DIM + k0;
        const __half* bp = g_cb16 + (size_t)nt0 * DIM + k0;
        #pragma unroll
        for (int i = 0; i < 2; i++) {
            int idx = i * 256 + tid;
            int row = idx >> 2;
            int seg = idx & 3;
            CP16(smb + 2u * (s * STAGE_H + row * AP + seg * 8),
                 ap + (size_t)row * DIM + seg * 8);
            CP16(smb + 2u * (s * STAGE_H + TILE_H + row * AP + seg * 8),
                 bp + (size_t)row * DIM + seg * 8);
        }
        CP_COMMIT();
    };

    issue(0, 0);

    #pragma unroll 1
    for (int ks = 0; ks < NKSTEP; ks++) {
        CP_WAIT0();
        __syncthreads();
        if (ks < NKSTEP - 1) issue((ks + 1) & 1, (ks + 1) * 32);

        const uint32_t* A32 = (const uint32_t*)(smh + (ks & 1) * STAGE_H);
        const uint32_t* B32 = A32 + TILE_H / 2;

        #pragma unroll
        for (int kl2 = 0; kl2 < 2; kl2++) {
            const int klh = kl2 * 8;
            uint32_t af[2][4], bf[8][2];
            #pragma unroll
            for (int mf = 0; mf < 2; mf++) {
                int m = mbase + mf * 16 + g;
                af[mf][0] = A32[m * (AP / 2) + klh + q];
                af[mf][1] = A32[(m + 8) * (AP / 2) + klh + q];
                af[mf][2] = A32[m * (AP / 2) + klh + 4 + q];
                af[mf][3] = A32[(m + 8) * (AP / 2) + klh + 4 + q];
            }
            #pragma unroll
            for (int nf = 0; nf < 8; nf++) {
                int n = nbase + nf * 8 + g;
                bf[nf][0] = B32[n * (AP / 2) + klh + q];
                bf[nf][1] = B32[n * (AP / 2) + klh + 4 + q];
            }
            #pragma unroll
            for (int mf = 0; mf < 2; mf++)
                #pragma unroll
                for (int nf = 0; nf < 8; nf++)
                    MMA_F16(acc[mf][nf], af[mf], bf[nf]);
        }
    }

    // epilogue: d_scan = fmaf(-2^-12, dot_scaled, cn); stage fp16 in smem.
    __syncthreads();
    #pragma unroll
    for (int mf = 0; mf < 2; mf++)
        #pragma unroll
        for (int h = 0; h < 2; h++) {
            int m = mbase + mf * 16 + g + h * 8;
            #pragma unroll
            for (int nf = 0; nf < 8; nf++) {
                int n = nbase + nf * 8 + q * 2;
                float d0 = fmaf(-0.000244140625f, acc[mf][nf][h * 2 + 0],
                                __ldg(&g_cbnorm[nt0 + n]));
                float d1 = fmaf(-0.000244140625f, acc[mf][nf][h * 2 + 1],
                                __ldg(&g_cbnorm[nt0 + n + 1]));
                *(__half2*)&smh[m * EPI_P + n] = __floats2half2_rn(d0, d1);
            }
        }
    __syncthreads();
    // per-token tile minimum (from the fp16-staged values the scan will see)
    if (tid < 128) {
        const __half2* rp = (const __half2*)&smh[tid * EPI_P];
        float mn = CUDART_INF_F;
        #pragma unroll
        for (int i = 0; i < 64; i++) {
            float2 f = __half22float2(rp[i]);
            mn = fminf(mn, fminf(f.x, f.y));
        }
        g_tmin[(size_t)ct * NTOK + tb * 128 + tid] = mn;  // [tile][token], coalesced
    }
    // store d_hh tile, coalesced
    __half* drow = g_dhh16 + (size_t)(tb * 128) * K_CODES + nt0;
    #pragma unroll
    for (int i = 0; i < 8; i++) {
        int idx = i * 256 + tid;
        int row = idx >> 4;
        int ch  = idx & 15;
        uint4 v = *(const uint4*)&smh[row * EPI_P + ch * 8];
        *(uint4*)(drow + (size_t)row * K_CODES + ch * 8) = v;
    }
}

// ---------------- scan (tile-min pruned) + rescore: one block per token ----------
#define MAXCAND 512
__global__ void __launch_bounds__(256, 4)
scan_rescore(const float* __restrict__ x, const float* __restrict__ cb,
             float* __restrict__ out) {
    __shared__ float stmin[NTILE];
    __shared__ int   sqtiles[NTILE];
    __shared__ int   sqcnt;
    __shared__ float sthr;
    __shared__ int   scnt;
    __shared__ int   scand[MAXCAND];
    __shared__ unsigned long long sbest;

    const int t = blockIdx.x;
    const int tid = threadIdx.x, lane = tid & 31, wid = tid >> 5;

    if (tid < NTILE) stmin[tid] = g_tmin[(size_t)tid * NTOK + t];
    if (tid == 0) { sqcnt = 0; scnt = 0; sbest = 0xFFFFFFFFFFFFFFFFull; }
    __syncthreads();

    if (wid == 0) {
        float mm = fminf(stmin[lane], stmin[lane + 32]);
        #pragma unroll
        for (int o = 16; o; o >>= 1) mm = fminf(mm, __shfl_down_sync(0xFFFFFFFFu, mm, o));
        if (lane == 0) sthr = mm + WINDOW;
    }
    __syncthreads();
    const float thr = sthr;

    if (tid < NTILE && stmin[tid] <= thr) {
        int p = atomicAdd(&sqcnt, 1);
        sqtiles[p] = tid;
    }
    __syncthreads();

    // phase 2: scan only qualifying tiles (one warp per tile)
    for (int qi = wid; qi < sqcnt; qi += 8) {
        int ct = sqtiles[qi];
        const __half2* dp = (const __half2*)(g_dhh16 + (size_t)t * K_CODES + ct * 128);
        #pragma unroll
        for (int i = 0; i < 2; i++) {
            float2 f = __half22float2(dp[lane + i * 32]);
            int base = ct * 128 + (lane + i * 32) * 2;
            if (f.x <= thr) {
                int p = atomicAdd(&scnt, 1);
                if (p < MAXCAND) scand[p] = base;
            }
            if (f.y <= thr) {
                int p = atomicAdd(&scnt, 1);
                if (p < MAXCAND) scand[p] = base + 1;
            }
        }
    }
    __syncthreads();
    int ncand = min(scnt, MAXCAND);

    const int b = t >> 10, hw = t & 1023;
    const float* xbase = x + (size_t)b * DIM * HW + hw;
    const float zn = g_znorm[t];

    for (int j = wid; j < ncand; j += 8) {
        int c = scand[j];
        const float* crow = cb + (size_t)c * DIM;
        double s = 0.0;
        #pragma unroll
        for (int i = 0; i < 8; i++) {
            int d = lane + i * 32;
            double xv = (double)__ldg(xbase + (size_t)d * HW);
            double cv = (double)__ldg(crow + d);
            s = fma(xv, cv, s);
        }
        #pragma unroll
        for (int o = 16; o; o >>= 1) s += __shfl_down_sync(0xFFFFFFFFu, s, o);
        if (lane == 0) {
            float dotf = (float)s;
            float t1 = __fadd_rn(zn, __ldg(&g_cbnorm[c]));
            float d  = __fsub_rn(t1, __fmul_rn(2.0f, dotf));
            unsigned int e = __float_as_uint(d);
            e = (e & 0x80000000u) ? ~e : (e | 0x80000000u);
            atomicMin(&sbest, ((unsigned long long)e << 32) | (unsigned int)c);
        }
    }
    __syncthreads();
    if (tid == 0) {
        int id = (int)(sbest & 0xFFFFFFFFull);
        g_idx[t] = id;
        out[OUT_IDX + t] = (float)id;
        atomicAdd(&g_counts[id], 1.0f);
    }
}

// ---------------- quantized output + loss + dw (fused, coalesced) ----------------
__global__ void quant_loss_dw(const float* __restrict__ x,
                              const float* __restrict__ cb,
                              float* __restrict__ out) {
    int c = blockIdx.x, b = blockIdx.y;
    int tid = threadIdx.x, lane = tid & 31;
    float ls = 0.0f;
    #pragma unroll
    for (int it = 0; it < 4; it++) {
        int hw = it * 256 + tid;
        int n  = (b << 10) + hw;
        int id = g_idx[n];
        float qv = __ldg(cb + (size_t)id * DIM + c);
        size_t off = (size_t)b * DIM * HW + (size_t)c * HW + hw;
        float xv = x[off];
        out[OUT_Q + off] = __fadd_rn(xv, __fsub_rn(qv, xv));
        float d = __fsub_rn(qv, xv);
        ls = fmaf(d, d, ls);
        atomicAdd(&g_dw[(size_t)id * DIM + c], xv);
    }
    double ds = (double)ls;
    #pragma unroll
    for (int o = 16; o; o >>= 1) ds += __shfl_down_sync(0xFFFFFFFFu, ds, o);
    if (lane == 0) atomicAdd(&g_loss, ds);
}

// ---------------- EMA finalize ----------------
__global__ void final_kernel(const float* __restrict__ ema_count,
                             const float* __restrict__ ema_weight,
                             float* __restrict__ out) {
    int k = blockIdx.x;
    int c = threadIdx.x;
    float nc = ema_count[k] * 0.95f + 0.05f * g_counts[k];
    const float denom = (float)(32768.0 + 8192.0 * 1e-5);
    nc = (nc + 1e-5f) / denom * 32768.0f;
    float w = ema_weight[(size_t)k * DIM + c] * 0.95f + 0.05f * g_dw[(size_t)k * DIM + c];
    out[OUT_W  + (size_t)k * DIM + c] = w;
    out[OUT_CB + (size_t)k * DIM + c] = w / nc;
    if (c == 0) out[OUT_CNT + k] = nc;
    if (k == 0 && c == 0) {
        double mean = g_loss / (double)((size_t)NTOK * DIM);
        out[OUT_LOSS] = 0.25f * (float)mean;
    }
}

extern "C" void kernel_launch(void* const* d_in, const int* in_sizes, int n_in,
                              void* d_out, int out_size) {
    const float* x          = (const float*)d_in[0];
    const float* cb         = (const float*)d_in[1];
    const float* ema_count  = (const float*)d_in[2];
    const float* ema_weight = (const float*)d_in[3];
    float* out = (float*)d_out;

    static int smem_set = 0;
    if (!smem_set) {
        cudaFuncSetAttribute(screen_gemm16,
                             cudaFuncAttributeMaxDynamicSharedMemorySize, SMEM_B);
        smem_set = 1;
    }

    init_kernel<<<(K_CODES * DIM + 255) / 256, 256>>>();
    decomp_x16T<<<dim3(HW / 32, DIM / 32, 32), dim3(32, 32)>>>(x);
    decomp_cb16<<<K_CODES * DIM / 256, 256>>>(cb);
    znorm_part<<<dim3(NTOK / 4 / 256, 16), 256>>>(x);
    znorm_comb<<<NTOK / 256, 256>>>();
    cbnorm_kernel<<<(K_CODES * 32 + 255) / 256, 256>>>(cb);
    screen_gemm16<<<dim3(K_CODES / 128, NTOK / 128), 256, SMEM_B>>>();
    scan_rescore<<<NTOK, 256>>>(x, cb, out);
    quant_loss_dw<<<dim3(DIM, 32), 256>>>(x, cb, out);
    final_kernel<<<K_CODES, DIM>>>(ema_count, ema_weight, out);
}